// round 2
// baseline (speedup 1.0000x reference)
#include <cuda_runtime.h>

#define T_LEN 2048
#define B_LEN 2048
#define HID   32
#define DF    8
#define DP    8
#define DS    24
#define WARPS_PER_CTA 4
#define NTHREADS (WARPS_PER_CTA * 32)
#define NB      4                      // batches per warp
#define NCTAS  (B_LEN / (WARPS_PER_CTA * NB))   // 128

typedef unsigned long long u64;

__device__ __forceinline__ float tanh_fast(float x) {
    float y;
    asm("tanh.approx.f32 %0, %1;" : "=f"(y) : "f"(x));
    return y;
}
// duplicate a scalar weight into a packed f32x2 operand (1 ALU instr)
__device__ __forceinline__ u64 pk2(float w) {
    u64 d;
    asm("mov.b64 %0, {%1, %1};" : "=l"(d) : "f"(w));
    return d;
}
// packed fused multiply-add: acc.{lo,hi} += a.{lo,hi} * b.{lo,hi}
__device__ __forceinline__ void fma2(u64& acc, u64 a, u64 b) {
    asm("fma.rn.f32x2 %0, %1, %2, %0;" : "+l"(acc) : "l"(a), "l"(b));
}
__device__ __forceinline__ u64 add2(u64 a, u64 b) {
    u64 d;
    asm("add.rn.f32x2 %0, %1, %2;" : "=l"(d) : "l"(a), "l"(b));
    return d;
}
__device__ __forceinline__ float2 unpk(u64 d) {
    float2 f;
    asm("mov.b64 {%0, %1}, %2;" : "=f"(f.x), "=f"(f.y) : "l"(d));
    return f;
}

struct __align__(16) WarpSmem {
    float4 hf[HID];
    float4 hp[HID];
    float4 hs0[HID];
    float4 hs1[HID];
    float4 hs2[HID];
    float4 xf[DF];
    float4 xp[DP];
    float4 xs[DS];
};

__global__ void __launch_bounds__(NTHREADS, 1)
chive_kernel(const float* __restrict__ frnn, const float* __restrict__ phrnn,
             const float* __restrict__ syl,
             const float* __restrict__ Wxf, const float* __restrict__ Whf,
             const float* __restrict__ bf,
             const float* __restrict__ Wxp, const float* __restrict__ Whp,
             const float* __restrict__ bp,
             const float* __restrict__ Wxs, const float* __restrict__ Whs,
             const float* __restrict__ bs,
             const int* __restrict__ fclock, const int* __restrict__ pclock,
             const int* __restrict__ sfreq,
             float* __restrict__ out)
{
    __shared__ unsigned char flags_sm[T_LEN];
    __shared__ WarpSmem wsm[WARPS_PER_CTA];

    const int tid = threadIdx.x;
    for (int t = tid; t < T_LEN; t += NTHREADS) {
        int fl = ((t % (fclock[t] + 1)) == 0) ? 1 : 0;
        if ((t % (pclock[t] + 1)) == 0) fl |= 2;
        if (sfreq[t] == 1) fl |= 4;
        flags_sm[t] = (unsigned char)fl;
    }
    __syncthreads();

    const int warp = tid >> 5;
    const int lane = tid & 31;
    const int b0 = (blockIdx.x * WARPS_PER_CTA + warp) * NB;

    WarpSmem& S = wsm[warp];
    const float4 z4 = make_float4(0.f, 0.f, 0.f, 0.f);
    S.hf[lane] = z4; S.hp[lane] = z4;
    S.hs0[lane] = z4; S.hs1[lane] = z4; S.hs2[lane] = z4;

    // Per-lane weight columns in registers (lane j holds column j).
    float wxf[DF], whf[HID], wxp[DP], whp[HID], wxs[HID], whs[HID];
    #pragma unroll
    for (int i = 0; i < DF; i++)  wxf[i] = Wxf[i * HID + lane];
    #pragma unroll
    for (int i = 0; i < HID; i++) whf[i] = Whf[i * HID + lane];
    #pragma unroll
    for (int i = 0; i < DP; i++)  wxp[i] = Wxp[i * HID + lane];
    #pragma unroll
    for (int i = 0; i < HID; i++) whp[i] = Whp[i * HID + lane];
    #pragma unroll
    for (int i = 0; i < HID; i++) wxs[i] = Wxs[i * HID + lane];
    #pragma unroll
    for (int i = 0; i < HID; i++) whs[i] = Whs[i * HID + lane];
    const float rbf = bf[lane], rbp = bp[lane], rbs = bs[lane];

    // Packed-view pointers onto the per-warp shared tiles.
    const ulonglong2* hf2  = (const ulonglong2*)S.hf;
    const ulonglong2* hp2  = (const ulonglong2*)S.hp;
    const ulonglong2* hs02 = (const ulonglong2*)S.hs0;
    const ulonglong2* hs12 = (const ulonglong2*)S.hs1;
    const ulonglong2* hs22 = (const ulonglong2*)S.hs2;
    const ulonglong2* xf2  = (const ulonglong2*)S.xf;
    const ulonglong2* xp2  = (const ulonglong2*)S.xp;
    const ulonglong2* xs2  = (const ulonglong2*)S.xs;

    // Current-step prefetched inputs.
    float fx[NB], px[NB], sx[NB];
    #pragma unroll
    for (int b = 0; b < NB; b++) { fx[b] = 0.f; px[b] = 0.f; sx[b] = 0.f; }
    {
        const int fl0 = flags_sm[0];
        if ((fl0 & 1) && lane < DF)
            #pragma unroll
            for (int b = 0; b < NB; b++) fx[b] = frnn[(size_t)(b0 + b) * DF + lane];
        if ((fl0 & 2) && lane < DP)
            #pragma unroll
            for (int b = 0; b < NB; b++) px[b] = phrnn[(size_t)(b0 + b) * DP + lane];
        if ((fl0 & 4) && lane < DS)
            #pragma unroll
            for (int b = 0; b < NB; b++) sx[b] = syl[(size_t)(b0 + b) * DS + lane];
    }
    __syncwarp();

    for (int t = 0; t < T_LEN; t++) {
        const int fl = flags_sm[t];

        // Prefetch inputs for t+1 (gated by its flags).
        float nf[NB], np[NB], ns[NB];
        #pragma unroll
        for (int b = 0; b < NB; b++) { nf[b] = 0.f; np[b] = 0.f; ns[b] = 0.f; }
        if (t + 1 < T_LEN) {
            const int nfl = flags_sm[t + 1];
            const size_t base = (size_t)(t + 1) * B_LEN;
            if ((nfl & 1) && lane < DF)
                #pragma unroll
                for (int b = 0; b < NB; b++) nf[b] = frnn[(base + b0 + b) * DF + lane];
            if ((nfl & 2) && lane < DP)
                #pragma unroll
                for (int b = 0; b < NB; b++) np[b] = phrnn[(base + b0 + b) * DP + lane];
            if ((nfl & 4) && lane < DS)
                #pragma unroll
                for (int b = 0; b < NB; b++) ns[b] = syl[(base + b0 + b) * DS + lane];
        }

        if (fl) {
            if ((fl & 1) && lane < DF) S.xf[lane] = make_float4(fx[0], fx[1], fx[2], fx[3]);
            if ((fl & 2) && lane < DP) S.xp[lane] = make_float4(px[0], px[1], px[2], px[3]);
            if ((fl & 4) && lane < DS) S.xs[lane] = make_float4(sx[0], sx[1], sx[2], sx[3]);
            __syncwarp();

            const bool wf = (fl & 1) != 0, wp = (fl & 2) != 0;
            float hfn[NB], hpn[NB];

            if (wf) {
                u64 a01 = pk2(rbf), a23 = pk2(rbf), c01 = 0ull, c23 = 0ull;
                #pragma unroll
                for (int i = 0; i < DF; i++) {
                    ulonglong2 x = xf2[i]; u64 w2 = pk2(wxf[i]);
                    if (i & 1) { fma2(c01, x.x, w2); fma2(c23, x.y, w2); }
                    else       { fma2(a01, x.x, w2); fma2(a23, x.y, w2); }
                }
                #pragma unroll
                for (int k = 0; k < HID; k++) {
                    ulonglong2 h = hf2[k]; u64 w2 = pk2(whf[k]);
                    if (k & 1) { fma2(c01, h.x, w2); fma2(c23, h.y, w2); }
                    else       { fma2(a01, h.x, w2); fma2(a23, h.y, w2); }
                }
                float2 u = unpk(add2(a01, c01)), v = unpk(add2(a23, c23));
                hfn[0] = tanh_fast(u.x); hfn[1] = tanh_fast(u.y);
                hfn[2] = tanh_fast(v.x); hfn[3] = tanh_fast(v.y);
            }
            if (wp) {
                u64 a01 = pk2(rbp), a23 = pk2(rbp), c01 = 0ull, c23 = 0ull;
                #pragma unroll
                for (int i = 0; i < DP; i++) {
                    ulonglong2 x = xp2[i]; u64 w2 = pk2(wxp[i]);
                    if (i & 1) { fma2(c01, x.x, w2); fma2(c23, x.y, w2); }
                    else       { fma2(a01, x.x, w2); fma2(a23, x.y, w2); }
                }
                #pragma unroll
                for (int k = 0; k < HID; k++) {
                    ulonglong2 h = hp2[k]; u64 w2 = pk2(whp[k]);
                    if (k & 1) { fma2(c01, h.x, w2); fma2(c23, h.y, w2); }
                    else       { fma2(a01, h.x, w2); fma2(a23, h.y, w2); }
                }
                float2 u = unpk(add2(a01, c01)), v = unpk(add2(a23, c23));
                hpn[0] = tanh_fast(u.x); hpn[1] = tanh_fast(u.y);
                hpn[2] = tanh_fast(v.x); hpn[3] = tanh_fast(v.y);
            }
            if (wf || wp) {
                __syncwarp();   // all lanes done reading old hf/hp
                if (wf) S.hf[lane] = make_float4(hfn[0], hfn[1], hfn[2], hfn[3]);
                if (wp) S.hp[lane] = make_float4(hpn[0], hpn[1], hpn[2], hpn[3]);
                __syncwarp();   // new hf/hp visible for s-cell
            }

            if (fl & 4) {
                u64 a0_01 = pk2(rbs), a0_23 = a0_01, c0_01 = 0ull, c0_23 = 0ull;
                u64 a1_01 = a0_01,    a1_23 = a0_01, c1_01 = 0ull, c1_23 = 0ull;
                u64 a2_01 = a0_01,    a2_23 = a0_01, c2_01 = 0ull, c2_23 = 0ull;
                #pragma unroll
                for (int k = 0; k < HID; k++) {
                    const u64 wx2 = pk2(wxs[k]), wh2 = pk2(whs[k]);
                    ulonglong2 xa = hf2[k];  fma2(a0_01, xa.x, wx2); fma2(a0_23, xa.y, wx2);
                    ulonglong2 ha = hs02[k]; fma2(c0_01, ha.x, wh2); fma2(c0_23, ha.y, wh2);
                    ulonglong2 xb = hp2[k];  fma2(a1_01, xb.x, wx2); fma2(a1_23, xb.y, wx2);
                    ulonglong2 hb = hs12[k]; fma2(c1_01, hb.x, wh2); fma2(c1_23, hb.y, wh2);
                    ulonglong2 hc = hs22[k]; fma2(c2_01, hc.x, wh2); fma2(c2_23, hc.y, wh2);
                }
                #pragma unroll
                for (int k = 0; k < DS; k++) {   // padded input: cols 24..31 are zero
                    ulonglong2 x = xs2[k]; u64 wx2 = pk2(wxs[k]);
                    fma2(a2_01, x.x, wx2); fma2(a2_23, x.y, wx2);
                }
                float2 u0 = unpk(add2(a0_01, c0_01)), v0 = unpk(add2(a0_23, c0_23));
                float2 u1 = unpk(add2(a1_01, c1_01)), v1 = unpk(add2(a1_23, c1_23));
                float2 u2 = unpk(add2(a2_01, c2_01)), v2 = unpk(add2(a2_23, c2_23));
                const float o00 = tanh_fast(u0.x), o01 = tanh_fast(u0.y),
                            o02 = tanh_fast(v0.x), o03 = tanh_fast(v0.y);
                const float o10 = tanh_fast(u1.x), o11 = tanh_fast(u1.y),
                            o12 = tanh_fast(v1.x), o13 = tanh_fast(v1.y);
                const float o20 = tanh_fast(u2.x), o21 = tanh_fast(u2.y),
                            o22 = tanh_fast(v2.x), o23 = tanh_fast(v2.y);
                __syncwarp();   // all lanes done reading old hs
                S.hs0[lane] = make_float4(o00, o01, o02, o03);
                S.hs1[lane] = make_float4(o10, o11, o12, o13);
                S.hs2[lane] = make_float4(o20, o21, o22, o23);
            }
        }

        #pragma unroll
        for (int b = 0; b < NB; b++) { fx[b] = nf[b]; px[b] = np[b]; sx[b] = ns[b]; }
    }

    // Emit final h_s [3, B, H]; lane j wrote its own slot, same-thread read is safe.
    const float4 r0 = S.hs0[lane];
    const float4 r1 = S.hs1[lane];
    const float4 r2 = S.hs2[lane];
    const float* rr0 = (const float*)&r0;
    const float* rr1 = (const float*)&r1;
    const float* rr2 = (const float*)&r2;
    #pragma unroll
    for (int b = 0; b < NB; b++) {
        out[((size_t)0 * B_LEN + b0 + b) * HID + lane] = rr0[b];
        out[((size_t)1 * B_LEN + b0 + b) * HID + lane] = rr1[b];
        out[((size_t)2 * B_LEN + b0 + b) * HID + lane] = rr2[b];
    }
}

extern "C" void kernel_launch(void* const* d_in, const int* in_sizes, int n_in,
                              void* d_out, int out_size) {
    (void)in_sizes; (void)n_in; (void)out_size;
    chive_kernel<<<NCTAS, NTHREADS>>>(
        (const float*)d_in[0],  (const float*)d_in[1],  (const float*)d_in[2],
        (const float*)d_in[3],  (const float*)d_in[4],  (const float*)d_in[5],
        (const float*)d_in[6],  (const float*)d_in[7],  (const float*)d_in[8],
        (const float*)d_in[9],  (const float*)d_in[10], (const float*)d_in[11],
        (const int*)d_in[12],   (const int*)d_in[13],   (const int*)d_in[14],
        (float*)d_out);
}

// round 4
// speedup vs baseline: 1.0029x; 1.0029x over previous
#include <cuda_runtime.h>

#define T_LEN 2048
#define B_LEN 2048
#define HID   32
#define DF    8
#define DP    8
#define DS    24
#define WARPS_PER_CTA 4
#define NTHREADS (WARPS_PER_CTA * 32)
#define NB      4                      // batches per warp (2 per half-warp group)
#define NCTAS  (B_LEN / (WARPS_PER_CTA * NB))   // 128

typedef unsigned long long u64;

__device__ __forceinline__ float tanh_fast(float x) {
    float y;
    asm("tanh.approx.f32 %0, %1;" : "=f"(y) : "f"(x));
    return y;
}
__device__ __forceinline__ u64 pk2(float w) {            // (w, w)
    u64 d; asm("mov.b64 %0, {%1, %1};" : "=l"(d) : "f"(w)); return d;
}
__device__ __forceinline__ u64 pack2(float lo, float hi) {
    u64 d; asm("mov.b64 %0, {%1, %2};" : "=l"(d) : "f"(lo), "f"(hi)); return d;
}
__device__ __forceinline__ void fma2(u64& acc, u64 a, u64 b) {
    asm("fma.rn.f32x2 %0, %1, %2, %0;" : "+l"(acc) : "l"(a), "l"(b));
}
__device__ __forceinline__ float2 unpk(u64 d) {
    float2 f; asm("mov.b64 {%0, %1}, %2;" : "=f"(f.x), "=f"(f.y) : "l"(d)); return f;
}

struct __align__(16) WarpSmem {
    float4 hf[HID];
    float4 hp[HID];
    float4 hs0[HID];
    float4 hs1[HID];
    float4 hs2[HID];
    float4 xf[DF];
    float4 xp[DP];
    float4 xs[DS];
};

__global__ void __launch_bounds__(NTHREADS, 1)
chive_kernel(const float* __restrict__ frnn, const float* __restrict__ phrnn,
             const float* __restrict__ syl,
             const float* __restrict__ Wxf, const float* __restrict__ Whf,
             const float* __restrict__ bf,
             const float* __restrict__ Wxp, const float* __restrict__ Whp,
             const float* __restrict__ bp,
             const float* __restrict__ Wxs, const float* __restrict__ Whs,
             const float* __restrict__ bs,
             const int* __restrict__ fclock, const int* __restrict__ pclock,
             const int* __restrict__ sfreq,
             float* __restrict__ out)
{
    __shared__ unsigned char flags_sm[T_LEN];
    __shared__ WarpSmem wsm[WARPS_PER_CTA];
    // f/p weight column-pairs, shared by all warps: w2[k][l] = (W[k][l], W[k][l+16])
    __shared__ float2 wxf2_s[DF * 16];
    __shared__ float2 whf2_s[HID * 16];
    __shared__ float2 wxp2_s[DP * 16];
    __shared__ float2 whp2_s[HID * 16];

    const int tid = threadIdx.x;
    for (int t = tid; t < T_LEN; t += NTHREADS) {
        int fl = ((t % (fclock[t] + 1)) == 0) ? 1 : 0;
        if ((t % (pclock[t] + 1)) == 0) fl |= 2;
        if (sfreq[t] == 1) fl |= 4;
        flags_sm[t] = (unsigned char)fl;
    }
    for (int i = tid; i < DF * 16; i += NTHREADS) {
        int k = i >> 4, l = i & 15;
        wxf2_s[i] = make_float2(Wxf[k * HID + l], Wxf[k * HID + l + 16]);
        wxp2_s[i] = make_float2(Wxp[k * HID + l], Wxp[k * HID + l + 16]);
    }
    for (int i = tid; i < HID * 16; i += NTHREADS) {
        int k = i >> 4, l = i & 15;
        whf2_s[i] = make_float2(Whf[k * HID + l], Whf[k * HID + l + 16]);
        whp2_s[i] = make_float2(Whp[k * HID + l], Whp[k * HID + l + 16]);
    }
    __syncthreads();

    const int warp = tid >> 5;
    const int lane = tid & 31;
    const int g    = lane >> 4;       // batch-group within warp (0/1)
    const int l    = lane & 15;       // j-lane: owns columns l and l+16
    const int b0 = (blockIdx.x * WARPS_PER_CTA + warp) * NB;  // warp's 4 batches

    WarpSmem& S = wsm[warp];
    const float4 z4 = make_float4(0.f, 0.f, 0.f, 0.f);
    S.hf[lane] = z4; S.hp[lane] = z4;
    S.hs0[lane] = z4; S.hs1[lane] = z4; S.hs2[lane] = z4;

    // s-cell weight columns in registers: both owned columns per lane.
    float wxs0[HID], wxs1[HID], whs0[HID], whs1[HID];
    #pragma unroll
    for (int k = 0; k < HID; k++) {
        wxs0[k] = Wxs[k * HID + l];
        wxs1[k] = Wxs[k * HID + l + 16];
        whs0[k] = Whs[k * HID + l];
        whs1[k] = Whs[k * HID + l + 16];
    }
    const float rbf0 = bf[l], rbf1 = bf[l + 16];
    const float rbp0 = bp[l], rbp1 = bp[l + 16];
    const float rbs0 = bs[l], rbs1 = bs[l + 16];

    // u64 views (pair = 2 batches) of the per-warp shared tiles.
    u64* hf64  = (u64*)S.hf;
    u64* hp64  = (u64*)S.hp;
    u64* hs064 = (u64*)S.hs0;
    u64* hs164 = (u64*)S.hs1;
    u64* hs264 = (u64*)S.hs2;
    const u64* xf64 = (const u64*)S.xf;
    const u64* xp64 = (const u64*)S.xp;
    const u64* xs64 = (const u64*)S.xs;

    // Current-step prefetched inputs (gated).
    float fx[NB], px[NB], sx[NB];
    #pragma unroll
    for (int b = 0; b < NB; b++) { fx[b] = 0.f; px[b] = 0.f; sx[b] = 0.f; }
    {
        const int fl0 = flags_sm[0];
        if ((fl0 & 1) && lane < DF)
            #pragma unroll
            for (int b = 0; b < NB; b++) fx[b] = frnn[(size_t)(b0 + b) * DF + lane];
        if ((fl0 & 2) && lane < DP)
            #pragma unroll
            for (int b = 0; b < NB; b++) px[b] = phrnn[(size_t)(b0 + b) * DP + lane];
        if ((fl0 & 4) && lane < DS)
            #pragma unroll
            for (int b = 0; b < NB; b++) sx[b] = syl[(size_t)(b0 + b) * DS + lane];
    }
    __syncwarp();

    for (int t = 0; t < T_LEN; t++) {
        const int fl = flags_sm[t];

        // Prefetch inputs for t+1 (gated by its flags).
        float nf[NB], np[NB], ns[NB];
        #pragma unroll
        for (int b = 0; b < NB; b++) { nf[b] = 0.f; np[b] = 0.f; ns[b] = 0.f; }
        if (t + 1 < T_LEN) {
            const int nfl = flags_sm[t + 1];
            const size_t base = (size_t)(t + 1) * B_LEN;
            if ((nfl & 1) && lane < DF)
                #pragma unroll
                for (int b = 0; b < NB; b++) nf[b] = frnn[(base + b0 + b) * DF + lane];
            if ((nfl & 2) && lane < DP)
                #pragma unroll
                for (int b = 0; b < NB; b++) np[b] = phrnn[(base + b0 + b) * DP + lane];
            if ((nfl & 4) && lane < DS)
                #pragma unroll
                for (int b = 0; b < NB; b++) ns[b] = syl[(base + b0 + b) * DS + lane];
        }

        if (fl) {
            if ((fl & 1) && lane < DF) S.xf[lane] = make_float4(fx[0], fx[1], fx[2], fx[3]);
            if ((fl & 2) && lane < DP) S.xp[lane] = make_float4(px[0], px[1], px[2], px[3]);
            if ((fl & 4) && lane < DS) S.xs[lane] = make_float4(sx[0], sx[1], sx[2], sx[3]);
            __syncwarp();

            const bool wf = (fl & 1) != 0, wp = (fl & 2) != 0;
            u64 of0 = 0ull, of1 = 0ull, op0 = 0ull, op1 = 0ull;

            if (wf) {
                u64 aA = pk2(rbf0), aB = pk2(rbf1);
                #pragma unroll
                for (int i = 0; i < DF; i++) {
                    const u64 x2 = xf64[2 * i + g];
                    const float2 w = wxf2_s[i * 16 + l];
                    fma2(aA, x2, pk2(w.x)); fma2(aB, x2, pk2(w.y));
                }
                #pragma unroll
                for (int k = 0; k < HID; k++) {
                    const u64 h2 = hf64[2 * k + g];
                    const float2 w = whf2_s[k * 16 + l];
                    fma2(aA, h2, pk2(w.x)); fma2(aB, h2, pk2(w.y));
                }
                const float2 uA = unpk(aA), uB = unpk(aB);
                of0 = pack2(tanh_fast(uA.x), tanh_fast(uA.y));
                of1 = pack2(tanh_fast(uB.x), tanh_fast(uB.y));
            }
            if (wp) {
                u64 aA = pk2(rbp0), aB = pk2(rbp1);
                #pragma unroll
                for (int i = 0; i < DP; i++) {
                    const u64 x2 = xp64[2 * i + g];
                    const float2 w = wxp2_s[i * 16 + l];
                    fma2(aA, x2, pk2(w.x)); fma2(aB, x2, pk2(w.y));
                }
                #pragma unroll
                for (int k = 0; k < HID; k++) {
                    const u64 h2 = hp64[2 * k + g];
                    const float2 w = whp2_s[k * 16 + l];
                    fma2(aA, h2, pk2(w.x)); fma2(aB, h2, pk2(w.y));
                }
                const float2 uA = unpk(aA), uB = unpk(aB);
                op0 = pack2(tanh_fast(uA.x), tanh_fast(uA.y));
                op1 = pack2(tanh_fast(uB.x), tanh_fast(uB.y));
            }
            if (wf || wp) {
                __syncwarp();   // all lanes done reading old hf/hp
                if (wf) { hf64[2 * l + g] = of0; hf64[2 * (l + 16) + g] = of1; }
                if (wp) { hp64[2 * l + g] = op0; hp64[2 * (l + 16) + g] = op1; }
                __syncwarp();   // new hf/hp visible for s-cell
            }

            if (fl & 4) {
                u64 a00 = pk2(rbs0), a01 = pk2(rbs1);   // row0 (x = hf)
                u64 a10 = a00,       a11 = a01;         // row1 (x = hp)
                u64 a20 = a00,       a21 = a01;         // row2 (x = xs)
                #pragma unroll
                for (int k = 0; k < HID; k++) {
                    const u64 wx0 = pk2(wxs0[k]), wx1 = pk2(wxs1[k]);
                    const u64 wh0 = pk2(whs0[k]), wh1 = pk2(whs1[k]);
                    const u64 hfv = hf64[2 * k + g];
                    fma2(a00, hfv, wx0); fma2(a01, hfv, wx1);
                    const u64 h0v = hs064[2 * k + g];
                    fma2(a00, h0v, wh0); fma2(a01, h0v, wh1);
                    const u64 hpv = hp64[2 * k + g];
                    fma2(a10, hpv, wx0); fma2(a11, hpv, wx1);
                    const u64 h1v = hs164[2 * k + g];
                    fma2(a10, h1v, wh0); fma2(a11, h1v, wh1);
                    const u64 h2v = hs264[2 * k + g];
                    fma2(a20, h2v, wh0); fma2(a21, h2v, wh1);
                }
                #pragma unroll
                for (int k = 0; k < DS; k++) {   // padded input cols 24..31 are zero
                    const u64 xv = xs64[2 * k + g];
                    fma2(a20, xv, pk2(wxs0[k])); fma2(a21, xv, pk2(wxs1[k]));
                }
                const float2 u00 = unpk(a00), u01 = unpk(a01);
                const float2 u10 = unpk(a10), u11 = unpk(a11);
                const float2 u20 = unpk(a20), u21 = unpk(a21);
                const u64 o00 = pack2(tanh_fast(u00.x), tanh_fast(u00.y));
                const u64 o01 = pack2(tanh_fast(u01.x), tanh_fast(u01.y));
                const u64 o10 = pack2(tanh_fast(u10.x), tanh_fast(u10.y));
                const u64 o11 = pack2(tanh_fast(u11.x), tanh_fast(u11.y));
                const u64 o20 = pack2(tanh_fast(u20.x), tanh_fast(u20.y));
                const u64 o21 = pack2(tanh_fast(u21.x), tanh_fast(u21.y));
                __syncwarp();   // all lanes done reading old hs
                hs064[2 * l + g] = o00; hs064[2 * (l + 16) + g] = o01;
                hs164[2 * l + g] = o10; hs164[2 * (l + 16) + g] = o11;
                hs264[2 * l + g] = o20; hs264[2 * (l + 16) + g] = o21;
            }
        }

        #pragma unroll
        for (int b = 0; b < NB; b++) { fx[b] = nf[b]; px[b] = np[b]; sx[b] = ns[b]; }
    }

    __syncwarp();   // hs written piecewise by other lanes — fence before epilogue
    const float4 r0 = S.hs0[lane];
    const float4 r1 = S.hs1[lane];
    const float4 r2 = S.hs2[lane];
    const float* rr0 = (const float*)&r0;
    const float* rr1 = (const float*)&r1;
    const float* rr2 = (const float*)&r2;
    #pragma unroll
    for (int b = 0; b < NB; b++) {
        out[((size_t)0 * B_LEN + b0 + b) * HID + lane] = rr0[b];
        out[((size_t)1 * B_LEN + b0 + b) * HID + lane] = rr1[b];
        out[((size_t)2 * B_LEN + b0 + b) * HID + lane] = rr2[b];
    }
}

extern "C" void kernel_launch(void* const* d_in, const int* in_sizes, int n_in,
                              void* d_out, int out_size) {
    (void)in_sizes; (void)n_in; (void)out_size;
    chive_kernel<<<NCTAS, NTHREADS>>>(
        (const float*)d_in[0],  (const float*)d_in[1],  (const float*)d_in[2],
        (const float*)d_in[3],  (const float*)d_in[4],  (const float*)d_in[5],
        (const float*)d_in[6],  (const float*)d_in[7],  (const float*)d_in[8],
        (const float*)d_in[9],  (const float*)d_in[10], (const float*)d_in[11],
        (const int*)d_in[12],   (const int*)d_in[13],   (const int*)d_in[14],
        (float*)d_out);
}